// round 16
// baseline (speedup 1.0000x reference)
#include <cuda_runtime.h>
#include <math.h>

// Problem constants
#define B_    128
#define N_    32
#define T_    50
#define H_    128
#define NT_   1600           // N_*T_
#define HOPS_ 8

// Output layout: tuple (BW, BA, neigh_r) flattened in order
#define BW_OFF   ((size_t)0)
#define BA_OFF   ((size_t)(B_) * NT_)                       // 204800
#define NR_OFF   (BA_OFF + (size_t)(B_) * HOPS_ * NT_)      // 204800 + 1638400

// ---- packed f32x2 helpers (Blackwell FFMA2 path, PTX-only) -----------------
__device__ __forceinline__ unsigned long long pack2(float lo, float hi) {
    unsigned long long r;
    asm("mov.b64 %0, {%1, %2};" : "=l"(r) : "f"(lo), "f"(hi));
    return r;
}
__device__ __forceinline__ void unpack2(unsigned long long v, float& lo, float& hi) {
    asm("mov.b64 {%0, %1}, %2;" : "=f"(lo), "=f"(hi) : "l"(v));
}
__device__ __forceinline__ unsigned long long mul2(unsigned long long a,
                                                   unsigned long long b) {
    unsigned long long d;
    asm("mul.rn.f32x2 %0, %1, %2;" : "=l"(d) : "l"(a), "l"(b));
    return d;
}
__device__ __forceinline__ unsigned long long ffma2(unsigned long long a,
                                                    unsigned long long b,
                                                    unsigned long long c) {
    unsigned long long d;
    asm("fma.rn.f32x2 %0, %1, %2, %3;" : "=l"(d) : "l"(a), "l"(b), "l"(c));
    return d;
}

// ---------------------------------------------------------------------------
// K1: fused neigh_r copy + logits + exp. (R10/R15 structure.)
// Block covers 16 n x 2 t = 32 rows of one b; 8 warps x 4 rows/warp sharing t
// -> node row u loaded ONCE per warp.
// CHANGE vs R15: __launch_bounds__(256, 4) -> regs capped at 64, 4 blocks/SM.
// PDL: trigger the dependent K2 launch at block end.
// ---------------------------------------------------------------------------
#define SA_  132
#define ST_  64

__global__ __launch_bounds__(256, 4) void k1_fused(
    const float* __restrict__ node,   // [B, T, H]
    const float* __restrict__ neigh,  // [B, N, T, H]
    const int*   __restrict__ nn,     // [B]
    const float* __restrict__ W,      // [HOPS, H]
    const float* __restrict__ bias,   // [HOPS]
    float* __restrict__ out)
{
    __shared__ float stage[HOPS_ * SA_];   // [hop][toff][nloc][k]

    const int tid  = threadIdx.x;
    const int wid  = tid >> 5;
    const int lane = tid & 31;

    // grid = B * 2 * 25 : bid -> (b, ng, tg)
    const int bid = blockIdx.x;
    const int b   = bid / 50;
    const int rem = bid - b * 50;
    const int ng  = rem / 25;            // 0..1  -> n0 = ng*16
    const int tg  = rem - ng * 25;       // 0..24 -> t0 = tg*2
    const int n0  = ng * 16;
    const int t0  = tg * 2;

    const int nh   = wid >> 1;           // 0..3 : n sub-group
    const int toff = wid & 1;            // 0..1 : t within block
    const int t    = t0 + toff;
    const int nA   = n0 + nh * 4;        // first n of this warp

    // W packed as hop-pairs: wp[a2][c] = {W[2a2][4l+c], W[2a2+1][4l+c]}
    unsigned long long wp[4][4];
#pragma unroll
    for (int a2 = 0; a2 < 4; a2++) {
        const float4 wa = __ldg((const float4*)(W + (2 * a2)     * H_) + lane);
        const float4 wb = __ldg((const float4*)(W + (2 * a2 + 1) * H_) + lane);
        wp[a2][0] = pack2(wa.x, wb.x);
        wp[a2][1] = pack2(wa.y, wb.y);
        wp[a2][2] = pack2(wa.z, wb.z);
        wp[a2][3] = pack2(wa.w, wb.w);
    }

    // base row = (b, nA, t); successive rows step n by 1 -> +T_*H_ floats
    const size_t row0 = ((size_t)(b * N_ + nA) * T_ + t) * H_;
    const float4* nbase = (const float4*)(neigh + row0) + lane;
    float4*       obase = (float4*)(out + NR_OFF + row0) + lane;

    // one node row per warp, reused for all 4 rows
    const float4 u = __ldg((const float4*)(node + ((size_t)b * T_ + t) * H_) + lane);

    // batched streaming loads (MLP) + streaming copy
    float4 v[4];
#pragma unroll
    for (int i = 0; i < 4; i++)
        v[i] = __ldcs(nbase + (size_t)i * (T_ * H_ / 4));
#pragma unroll
    for (int i = 0; i < 4; i++)
        __stcs(obase + (size_t)i * (T_ * H_ / 4), v[i]);

#pragma unroll
    for (int i = 0; i < 4; i++) {
        const int nloc = nh * 4 + i;     // 0..15

        const float px = v[i].x * u.x, py = v[i].y * u.y,
                    pz = v[i].z * u.z, pw = v[i].w * u.w;
        const unsigned long long d0 = pack2(px, px);
        const unsigned long long d1 = pack2(py, py);
        const unsigned long long d2 = pack2(pz, pz);
        const unsigned long long d3 = pack2(pw, pw);

        unsigned long long acc[4];
#pragma unroll
        for (int a2 = 0; a2 < 4; a2++) {
            acc[a2] = mul2(d0, wp[a2][0]);
            acc[a2] = ffma2(d1, wp[a2][1], acc[a2]);
            acc[a2] = ffma2(d2, wp[a2][2], acc[a2]);
            acc[a2] = ffma2(d3, wp[a2][3], acc[a2]);
        }

        float part[HOPS_];
        unpack2(acc[0], part[0], part[1]);
        unpack2(acc[1], part[2], part[3]);
        unpack2(acc[2], part[4], part[5]);
        unpack2(acc[3], part[6], part[7]);

        // ---- 14-shuffle fold reduction: stop at 4 residue-partials/hop ----
#pragma unroll
        for (int a = 0; a < HOPS_; a++)
            part[a] += __shfl_xor_sync(0xffffffffu, part[a], 16);

        float q0 = (lane < 16) ? part[0] : part[4];
        float q1 = (lane < 16) ? part[1] : part[5];
        float q2 = (lane < 16) ? part[2] : part[6];
        float q3 = (lane < 16) ? part[3] : part[7];
        q0 += __shfl_xor_sync(0xffffffffu, q0, 8);
        q1 += __shfl_xor_sync(0xffffffffu, q1, 8);
        q2 += __shfl_xor_sync(0xffffffffu, q2, 8);
        q3 += __shfl_xor_sync(0xffffffffu, q3, 8);

        float r0 = ((lane & 8) == 0) ? q0 : q2;
        float r1 = ((lane & 8) == 0) ? q1 : q3;
        r0 += __shfl_xor_sync(0xffffffffu, r0, 4);
        r1 += __shfl_xor_sync(0xffffffffu, r1, 4);

        // lane l holds residue-partial k=(l&3) of hop a=(l>>2)
        const float s = ((lane & 4) == 0) ? r0 : r1;
        stage[(lane >> 2) * SA_ + toff * ST_ + nloc * 4 + (lane & 3)] = s;
    }
    __syncthreads();

    // epilogue: 256 threads finish 8 hops x 32 (n,t): LDS.128 + 3 FADD + exp
    {
        const int a    = tid >> 5;                 // hop
        const int j    = tid & 31;                 // row slot
        const int tofe = j >> 4;                   // 0..1
        const int nle  = j & 15;                   // 0..15
        const float4 p = *(const float4*)&stage[a * SA_ + tofe * ST_ + nle * 4];
        const float dot = (p.x + p.y) + (p.z + p.w);
        const float rscale = rsqrtf((float)__ldg(nn));
        const float logit = (dot + __ldg(bias + a)) * rscale;
        // exp without max-subtraction: logits are O(1) by construction,
        // normalization cancels any shift exactly.
        out[BA_OFF + ((size_t)(b * HOPS_ + a)) * NT_
            + (size_t)(n0 + nle) * T_ + t0 + tofe] = __expf(logit);
    }

    // PDL: allow the dependent K2 grid to begin launching
    cudaTriggerProgrammaticLaunchCompletion();
}

// ---------------------------------------------------------------------------
// K2: SINGLE-PASS per-b softmax-normalize + BW. (unchanged from R10/R15)
// One block per b, 512 threads; thread s<400 owns float4 slot s of ALL 8 hops.
// PDL: grid-dependency sync at the head (K1 writes must be visible).
// ---------------------------------------------------------------------------
#define KSA_ 68   // stage stride per hop: bank = 4a + 4wid + k (conflict-free)

__global__ __launch_bounds__(512) void k2_softmax_bw(float* __restrict__ out)
{
    __shared__ float stage[HOPS_ * KSA_];   // [hop][wid*4 + k]
    __shared__ float inv_s[HOPS_];

    cudaGridDependencySynchronize();        // wait for K1 completion/visibility

    const int tid  = threadIdx.x;
    const int wid  = tid >> 5;              // 0..15
    const int lane = tid & 31;
    const int b    = blockIdx.x;
    const bool act = tid < NT_ / 4;         // 400 active slots

    float* BAb = out + BA_OFF + (size_t)b * HOPS_ * NT_;

    // ---- load all 8 hops' float4 for this slot (batched, MLP=8) ----
    float4 va[HOPS_];
#pragma unroll
    for (int a = 0; a < HOPS_; a++)
        va[a] = act ? ((const float4*)(BAb + (size_t)a * NT_))[tid]
                    : make_float4(0.f, 0.f, 0.f, 0.f);

    // ---- per-hop partial sums ----
    float part[HOPS_];
#pragma unroll
    for (int a = 0; a < HOPS_; a++)
        part[a] = (va[a].x + va[a].y) + (va[a].z + va[a].w);

    // ---- 14-shuffle fold reduction: 8 sums over 32 lanes -> 4 residues/hop
#pragma unroll
    for (int a = 0; a < HOPS_; a++)
        part[a] += __shfl_xor_sync(0xffffffffu, part[a], 16);

    float q0 = (lane < 16) ? part[0] : part[4];
    float q1 = (lane < 16) ? part[1] : part[5];
    float q2 = (lane < 16) ? part[2] : part[6];
    float q3 = (lane < 16) ? part[3] : part[7];
    q0 += __shfl_xor_sync(0xffffffffu, q0, 8);
    q1 += __shfl_xor_sync(0xffffffffu, q1, 8);
    q2 += __shfl_xor_sync(0xffffffffu, q2, 8);
    q3 += __shfl_xor_sync(0xffffffffu, q3, 8);

    float r0 = ((lane & 8) == 0) ? q0 : q2;
    float r1 = ((lane & 8) == 0) ? q1 : q3;
    r0 += __shfl_xor_sync(0xffffffffu, r0, 4);
    r1 += __shfl_xor_sync(0xffffffffu, r1, 4);

    // lane l holds residue k=(l&3) of hop a=(l>>2)
    const float s = ((lane & 4) == 0) ? r0 : r1;
    stage[(lane >> 2) * KSA_ + wid * 4 + (lane & 3)] = s;
    __syncthreads();

    // ---- 8 warps finish: warp a reduces 64 residues of hop a (fixed order)
    if (wid < HOPS_) {
        float t = stage[wid * KSA_ + lane] + stage[wid * KSA_ + 32 + lane];
#pragma unroll
        for (int off = 16; off; off >>= 1)
            t += __shfl_xor_sync(0xffffffffu, t, off);
        if (lane == 0) inv_s[wid] = 1.0f / t;
    }
    __syncthreads();

    // ---- normalize registers, store BA + BW ----
    if (act) {
        float4 acc = make_float4(0.f, 0.f, 0.f, 0.f);
#pragma unroll
        for (int a = 0; a < HOPS_; a++) {
            const float iv = inv_s[a];
            float4 v = va[a];
            v.x *= iv; v.y *= iv; v.z *= iv; v.w *= iv;
            ((float4*)(BAb + (size_t)a * NT_))[tid] = v;
            acc.x += v.x; acc.y += v.y; acc.z += v.z; acc.w += v.w;
        }
        ((float4*)(out + (size_t)b * NT_))[tid] = acc;   // BW
    }
}

// ---------------------------------------------------------------------------
extern "C" void kernel_launch(void* const* d_in, const int* in_sizes, int n_in,
                              void* d_out, int out_size)
{
    const float* node  = (const float*)d_in[0];  // [B,T,H]
    const float* neigh = (const float*)d_in[1];  // [B,N,T,H]
    const int*   nn    = (const int*)  d_in[2];  // [B]
    const float* W     = (const float*)d_in[3];  // [HOPS,H]
    const float* bias  = (const float*)d_in[4];  // [HOPS]
    float* out = (float*)d_out;

    (void)in_sizes; (void)n_in; (void)out_size;

    // K1: grid = B * 2 * 25 = 6400 blocks (16 n x 2 t per block)
    k1_fused<<<B_ * 50, 256>>>(node, neigh, nn, W, bias, out);

    // K2 with Programmatic Dependent Launch: overlap launch with K1 tail
    cudaLaunchConfig_t cfg = {};
    cfg.gridDim  = dim3(B_);
    cfg.blockDim = dim3(512);
    cfg.dynamicSmemBytes = 0;
    cudaLaunchAttribute attrs[1];
    attrs[0].id = cudaLaunchAttributeProgrammaticStreamSerialization;
    attrs[0].val.programmaticStreamSerializationAllowed = 1;
    cfg.attrs = attrs;
    cfg.numAttrs = 1;
    cudaLaunchKernelEx(&cfg, k2_softmax_bw, out);
}

// round 17
// speedup vs baseline: 1.0007x; 1.0007x over previous
#include <cuda_runtime.h>
#include <math.h>

// Problem constants
#define B_    128
#define N_    32
#define T_    50
#define H_    128
#define NT_   1600           // N_*T_
#define HOPS_ 8

// Output layout: tuple (BW, BA, neigh_r) flattened in order
#define BW_OFF   ((size_t)0)
#define BA_OFF   ((size_t)(B_) * NT_)                       // 204800
#define NR_OFF   (BA_OFF + (size_t)(B_) * HOPS_ * NT_)      // 204800 + 1638400

// ---- packed f32x2 helpers (Blackwell FFMA2 path, PTX-only) -----------------
__device__ __forceinline__ unsigned long long pack2(float lo, float hi) {
    unsigned long long r;
    asm("mov.b64 %0, {%1, %2};" : "=l"(r) : "f"(lo), "f"(hi));
    return r;
}
__device__ __forceinline__ void unpack2(unsigned long long v, float& lo, float& hi) {
    asm("mov.b64 {%0, %1}, %2;" : "=f"(lo), "=f"(hi) : "l"(v));
}
__device__ __forceinline__ unsigned long long mul2(unsigned long long a,
                                                   unsigned long long b) {
    unsigned long long d;
    asm("mul.rn.f32x2 %0, %1, %2;" : "=l"(d) : "l"(a), "l"(b));
    return d;
}
__device__ __forceinline__ unsigned long long ffma2(unsigned long long a,
                                                    unsigned long long b,
                                                    unsigned long long c) {
    unsigned long long d;
    asm("fma.rn.f32x2 %0, %1, %2, %3;" : "=l"(d) : "l"(a), "l"(b), "l"(c));
    return d;
}

// ---------------------------------------------------------------------------
// K1: fused neigh_r copy + logits + exp. (R15 structure — proven best.)
// Block covers 16 n x 2 t = 32 rows of one b; 8 warps x 4 rows/warp sharing t
// -> node row u loaded ONCE per warp. PDL trigger at block end.
// ---------------------------------------------------------------------------
#define SA_  132
#define ST_  64

__global__ __launch_bounds__(256, 3) void k1_fused(
    const float* __restrict__ node,   // [B, T, H]
    const float* __restrict__ neigh,  // [B, N, T, H]
    const int*   __restrict__ nn,     // [B]
    const float* __restrict__ W,      // [HOPS, H]
    const float* __restrict__ bias,   // [HOPS]
    float* __restrict__ out)
{
    __shared__ float stage[HOPS_ * SA_];   // [hop][toff][nloc][k]

    const int tid  = threadIdx.x;
    const int wid  = tid >> 5;
    const int lane = tid & 31;

    // grid = B * 2 * 25 : bid -> (b, ng, tg)
    const int bid = blockIdx.x;
    const int b   = bid / 50;
    const int rem = bid - b * 50;
    const int ng  = rem / 25;            // 0..1  -> n0 = ng*16
    const int tg  = rem - ng * 25;       // 0..24 -> t0 = tg*2
    const int n0  = ng * 16;
    const int t0  = tg * 2;

    const int nh   = wid >> 1;           // 0..3 : n sub-group
    const int toff = wid & 1;            // 0..1 : t within block
    const int t    = t0 + toff;
    const int nA   = n0 + nh * 4;        // first n of this warp

    // W packed as hop-pairs: wp[a2][c] = {W[2a2][4l+c], W[2a2+1][4l+c]}
    unsigned long long wp[4][4];
#pragma unroll
    for (int a2 = 0; a2 < 4; a2++) {
        const float4 wa = __ldg((const float4*)(W + (2 * a2)     * H_) + lane);
        const float4 wb = __ldg((const float4*)(W + (2 * a2 + 1) * H_) + lane);
        wp[a2][0] = pack2(wa.x, wb.x);
        wp[a2][1] = pack2(wa.y, wb.y);
        wp[a2][2] = pack2(wa.z, wb.z);
        wp[a2][3] = pack2(wa.w, wb.w);
    }

    // base row = (b, nA, t); successive rows step n by 1 -> +T_*H_ floats
    const size_t row0 = ((size_t)(b * N_ + nA) * T_ + t) * H_;
    const float4* nbase = (const float4*)(neigh + row0) + lane;
    float4*       obase = (float4*)(out + NR_OFF + row0) + lane;

    // one node row per warp, reused for all 4 rows
    const float4 u = __ldg((const float4*)(node + ((size_t)b * T_ + t) * H_) + lane);

    // batched streaming loads (MLP) + streaming copy
    float4 v[4];
#pragma unroll
    for (int i = 0; i < 4; i++)
        v[i] = __ldcs(nbase + (size_t)i * (T_ * H_ / 4));
#pragma unroll
    for (int i = 0; i < 4; i++)
        __stcs(obase + (size_t)i * (T_ * H_ / 4), v[i]);

#pragma unroll
    for (int i = 0; i < 4; i++) {
        const int nloc = nh * 4 + i;     // 0..15

        const float px = v[i].x * u.x, py = v[i].y * u.y,
                    pz = v[i].z * u.z, pw = v[i].w * u.w;
        const unsigned long long d0 = pack2(px, px);
        const unsigned long long d1 = pack2(py, py);
        const unsigned long long d2 = pack2(pz, pz);
        const unsigned long long d3 = pack2(pw, pw);

        unsigned long long acc[4];
#pragma unroll
        for (int a2 = 0; a2 < 4; a2++) {
            acc[a2] = mul2(d0, wp[a2][0]);
            acc[a2] = ffma2(d1, wp[a2][1], acc[a2]);
            acc[a2] = ffma2(d2, wp[a2][2], acc[a2]);
            acc[a2] = ffma2(d3, wp[a2][3], acc[a2]);
        }

        float part[HOPS_];
        unpack2(acc[0], part[0], part[1]);
        unpack2(acc[1], part[2], part[3]);
        unpack2(acc[2], part[4], part[5]);
        unpack2(acc[3], part[6], part[7]);

        // ---- 14-shuffle fold reduction: stop at 4 residue-partials/hop ----
#pragma unroll
        for (int a = 0; a < HOPS_; a++)
            part[a] += __shfl_xor_sync(0xffffffffu, part[a], 16);

        float q0 = (lane < 16) ? part[0] : part[4];
        float q1 = (lane < 16) ? part[1] : part[5];
        float q2 = (lane < 16) ? part[2] : part[6];
        float q3 = (lane < 16) ? part[3] : part[7];
        q0 += __shfl_xor_sync(0xffffffffu, q0, 8);
        q1 += __shfl_xor_sync(0xffffffffu, q1, 8);
        q2 += __shfl_xor_sync(0xffffffffu, q2, 8);
        q3 += __shfl_xor_sync(0xffffffffu, q3, 8);

        float r0 = ((lane & 8) == 0) ? q0 : q2;
        float r1 = ((lane & 8) == 0) ? q1 : q3;
        r0 += __shfl_xor_sync(0xffffffffu, r0, 4);
        r1 += __shfl_xor_sync(0xffffffffu, r1, 4);

        // lane l holds residue-partial k=(l&3) of hop a=(l>>2)
        const float s = ((lane & 4) == 0) ? r0 : r1;
        stage[(lane >> 2) * SA_ + toff * ST_ + nloc * 4 + (lane & 3)] = s;
    }
    __syncthreads();

    // epilogue: 256 threads finish 8 hops x 32 (n,t): LDS.128 + 3 FADD + exp
    {
        const int a    = tid >> 5;                 // hop
        const int j    = tid & 31;                 // row slot
        const int tofe = j >> 4;                   // 0..1
        const int nle  = j & 15;                   // 0..15
        const float4 p = *(const float4*)&stage[a * SA_ + tofe * ST_ + nle * 4];
        const float dot = (p.x + p.y) + (p.z + p.w);
        const float rscale = rsqrtf((float)__ldg(nn));
        const float logit = (dot + __ldg(bias + a)) * rscale;
        // exp without max-subtraction: logits are O(1) by construction,
        // normalization cancels any shift exactly.
        out[BA_OFF + ((size_t)(b * HOPS_ + a)) * NT_
            + (size_t)(n0 + nle) * T_ + t0 + tofe] = __expf(logit);
    }

    // PDL: allow the dependent K2 grid to begin launching
    cudaTriggerProgrammaticLaunchCompletion();
}

// ---------------------------------------------------------------------------
// K2: 1024-thread hop-split softmax-normalize + BW. One block per b.
// Thread (s, half): half owns hops 4*half..4*half+3 of float4 slot s.
// Serial load chain 8 -> 4; occupancy 25% -> 50%; sums + BW in fixed order.
// PDL: grid-dependency sync at the head.
// ---------------------------------------------------------------------------
__global__ __launch_bounds__(1024) void k2_softmax_bw(float* __restrict__ out)
{
    __shared__ float  red[HOPS_][16];    // per-warp hop partials
    __shared__ float  inv_s[HOPS_];
    __shared__ float4 accs[400];         // half1 partial BW

    cudaGridDependencySynchronize();     // wait for K1 completion/visibility

    const int tid  = threadIdx.x;
    const int warp = tid >> 5;           // 0..31
    const int lane = tid & 31;
    const int half = tid >> 9;           // 0: hops 0-3, 1: hops 4-7
    const int s    = tid & 511;          // float4 slot
    const bool act = s < NT_ / 4;        // 400 active slots per half
    const int a0   = half * 4;
    const int b    = blockIdx.x;

    float* BAb = out + BA_OFF + (size_t)b * HOPS_ * NT_;

    // ---- load this half's 4 hops for slot s (batched, MLP=4) ----
    float4 va[4];
#pragma unroll
    for (int k = 0; k < 4; k++)
        va[k] = act ? ((const float4*)(BAb + (size_t)(a0 + k) * NT_))[s]
                    : make_float4(0.f, 0.f, 0.f, 0.f);

    // ---- per-hop partial sums ----
    float p0 = (va[0].x + va[0].y) + (va[0].z + va[0].w);
    float p1 = (va[1].x + va[1].y) + (va[1].z + va[1].w);
    float p2 = (va[2].x + va[2].y) + (va[2].z + va[2].w);
    float p3 = (va[3].x + va[3].y) + (va[3].z + va[3].w);

    // ---- 9-shuffle fold reduction: 4 sums over 32 lanes ----
    p0 += __shfl_xor_sync(0xffffffffu, p0, 16);
    p1 += __shfl_xor_sync(0xffffffffu, p1, 16);
    p2 += __shfl_xor_sync(0xffffffffu, p2, 16);
    p3 += __shfl_xor_sync(0xffffffffu, p3, 16);

    float q0 = (lane < 16) ? p0 : p2;
    float q1 = (lane < 16) ? p1 : p3;
    q0 += __shfl_xor_sync(0xffffffffu, q0, 8);
    q1 += __shfl_xor_sync(0xffffffffu, q1, 8);

    float r = ((lane & 8) == 0) ? q0 : q1;
    r += __shfl_xor_sync(0xffffffffu, r, 4);
    r += __shfl_xor_sync(0xffffffffu, r, 2);
    r += __shfl_xor_sync(0xffffffffu, r, 1);
    // lane group k*8 holds sum for hop a0 + k, k = lane>>3
    if ((lane & 7) == 0)
        red[a0 + (lane >> 3)][warp & 15] = r;
    __syncthreads();

    // ---- 8 warps finish: warp a reduces its 16 per-warp partials ----
    if (warp < HOPS_) {
        float t = (lane < 16) ? red[warp][lane] : 0.f;
        t += __shfl_xor_sync(0xffffffffu, t, 8);
        t += __shfl_xor_sync(0xffffffffu, t, 4);
        t += __shfl_xor_sync(0xffffffffu, t, 2);
        t += __shfl_xor_sync(0xffffffffu, t, 1);
        if (lane == 0) inv_s[warp] = 1.0f / t;
    }
    __syncthreads();

    // ---- normalize registers, store BA; stage half1's BW partial ----
    float4 bw = make_float4(0.f, 0.f, 0.f, 0.f);
    if (act) {
#pragma unroll
        for (int k = 0; k < 4; k++) {
            const float iv = inv_s[a0 + k];
            float4 x = va[k];
            x.x *= iv; x.y *= iv; x.z *= iv; x.w *= iv;
            ((float4*)(BAb + (size_t)(a0 + k) * NT_))[s] = x;
            bw.x += x.x; bw.y += x.y; bw.z += x.z; bw.w += x.w;
        }
        if (half == 1) accs[s] = bw;
    }
    __syncthreads();

    // ---- half0 combines (hops 0-3) + (hops 4-7) in fixed order -> BW ----
    if (act && half == 0) {
        const float4 o = accs[s];
        bw.x += o.x; bw.y += o.y; bw.z += o.z; bw.w += o.w;
        ((float4*)(out + (size_t)b * NT_))[s] = bw;
    }
}

// ---------------------------------------------------------------------------
extern "C" void kernel_launch(void* const* d_in, const int* in_sizes, int n_in,
                              void* d_out, int out_size)
{
    const float* node  = (const float*)d_in[0];  // [B,T,H]
    const float* neigh = (const float*)d_in[1];  // [B,N,T,H]
    const int*   nn    = (const int*)  d_in[2];  // [B]
    const float* W     = (const float*)d_in[3];  // [HOPS,H]
    const float* bias  = (const float*)d_in[4];  // [HOPS]
    float* out = (float*)d_out;

    (void)in_sizes; (void)n_in; (void)out_size;

    // K1: grid = B * 2 * 25 = 6400 blocks (16 n x 2 t per block)
    k1_fused<<<B_ * 50, 256>>>(node, neigh, nn, W, bias, out);

    // K2 with Programmatic Dependent Launch: overlap launch with K1 tail
    cudaLaunchConfig_t cfg = {};
    cfg.gridDim  = dim3(B_);
    cfg.blockDim = dim3(1024);
    cfg.dynamicSmemBytes = 0;
    cudaLaunchAttribute attrs[1];
    attrs[0].id = cudaLaunchAttributeProgrammaticStreamSerialization;
    attrs[0].val.programmaticStreamSerializationAllowed = 1;
    cfg.attrs = attrs;
    cfg.numAttrs = 1;
    cudaLaunchKernelEx(&cfg, k2_softmax_bw, out);
}